// round 13
// baseline (speedup 1.0000x reference)
#include <cuda_runtime.h>

#define BB 64
#define VV 2000
#define FF 8
#define GG 80
#define NRR 5               // distinct mu_rho  (g = r*16 + t)
#define NTT 16              // distinct mu_theta
#define NROT 5
#define DD (FF*GG)          // 640
#define VCH 10              // vertex chunks per (b-pair, k)
#define VCS (VV/VCH)        // 200
#define NSLICE 4
#define TPB (GG*NSLICE)     // 320 threads kernel A
#define TPBB 256            // kernel B: 64 j-lanes x 4 i-segments
#define JT 10               // j tiles of 64
#define BG 32               // b groups of 2
#define TWO_PI_F 6.283185307179586f
#define EPSF 1e-5f
#define NLOG2E -1.4426950408889634f

// partial (unnormalized) sums: [bk][chunk][9][G]  (0: sum w; 1..8: sum w*feat)
__device__ float g_part[BB*NROT][VCH][9][GG];
// normalized descriptors: [bk][f*G+g]
__device__ __align__(16) float g_desc[BB*NROT][DD];

// ---------------- helpers ----------------
__device__ __forceinline__ unsigned long long pack2(float lo, float hi) {
    unsigned long long r;
    asm("mov.b64 %0, {%1, %2};" : "=l"(r) : "f"(lo), "f"(hi));
    return r;
}
__device__ __forceinline__ void fma2(unsigned long long& d,
                                     unsigned long long a, unsigned long long b) {
    asm("fma.rn.f32x2 %0, %1, %2, %3;" : "=l"(d) : "l"(a), "l"(b), "l"(d));
}
__device__ __forceinline__ void add2(unsigned long long& d, unsigned long long a) {
    asm("add.rn.f32x2 %0, %1, %2;" : "=l"(d) : "l"(d), "l"(a));
}
__device__ __forceinline__ unsigned long long mul2(unsigned long long a,
                                                   unsigned long long b) {
    unsigned long long r;
    asm("mul.rn.f32x2 %0, %1, %2;" : "=l"(r) : "l"(a), "l"(b));
    return r;
}
__device__ __forceinline__ float2 unpack2(unsigned long long v) {
    float lo, hi;
    asm("mov.b64 {%0, %1}, %2;" : "=f"(lo), "=f"(hi) : "l"(v));
    return make_float2(lo, hi);
}
__device__ __forceinline__ float ex2(float x) {
    float r;
    asm("ex2.approx.f32 %0, %1;" : "=f"(r) : "f"(x));
    return r;
}

// ---------------------------------------------------------------------------
// Kernel A: separable gaussians, TWO BATCHES packed per block.
// T, R*mask, feat all staged as float2{b0, b1}; w2 = mul2(T2, R2) yields both
// batches' weights in one instr (no pack movs); 9 packed accumulators.
// Per iter: 6 LDS + 1 mul2 + 1 add2 + 8 fma2 for 2 (v,g,k,b) units.
// ---------------------------------------------------------------------------
__global__ void __launch_bounds__(TPB, 4)
gauss_desc_kernel(const float* __restrict__ feat,
                  const float* __restrict__ rho,
                  const float* __restrict__ theta,
                  const float* __restrict__ mask,
                  const float* __restrict__ mu_rho,
                  const float* __restrict__ sigma_rho,
                  const float* __restrict__ mu_theta,
                  const float* __restrict__ sigma_theta)
{
    extern __shared__ float sm[];
    float2* s_T2 = (float2*)sm;              // [VCS*16] {b0,b1}   25600 B
    float2* s_R2 = (float2*)(sm + 6400);     // [VCS*5]  {b0,b1}    8000 B
    float2* s_F2 = (float2*)(sm + 8400);     // [VCS*8]  {b0,b1}   12800 B
    float2* s_th = (float2*)(sm + 11600);    // [VCS]    {b0,b1}    1600 B
                                             // total              48000 B

    const int bkk = blockIdx.x;
    const int bp  = bkk / NROT;
    const int k   = bkk - bp*NROT;
    const int b0  = bp*2;
    const int b1  = b0 + 1;
    const int cv0 = blockIdx.y * VCS;
    const int tid = threadIdx.x;
    const float kd = (float)k * (TWO_PI_F / (float)NROT);

    // hoisted gaussian params (staging only)
    float mur[NRR], nisr[NRR];
    #pragma unroll
    for (int r = 0; r < NRR; r++) {
        float m = mu_rho[r*NTT];             // grid: constant across t
        float s = sigma_rho[r*NTT];
        mur[r]  = m;
        nisr[r] = NLOG2E / (s*s + EPSF);
    }
    const int t0 = tid & 15;
    const float mut0  = mu_theta[t0];
    const float st0   = sigma_theta[t0];
    const float nist0 = NLOG2E / (st0*st0 + EPSF);

    // phase 1: per-vertex rotated thetas + rho gaussians * mask, both batches
    for (int v = tid; v < VCS; v += TPB) {
        float ta = theta[b0*VV + cv0 + v] + kd; if (ta >= TWO_PI_F) ta -= TWO_PI_F;
        float tb = theta[b1*VV + cv0 + v] + kd; if (tb >= TWO_PI_F) tb -= TWO_PI_F;
        s_th[v] = make_float2(ta, tb);
        float r0 = rho[b0*VV + cv0 + v];
        float r1 = rho[b1*VV + cv0 + v];
        float m0 = mask[b0*VV + cv0 + v];
        float m1 = mask[b1*VV + cv0 + v];
        #pragma unroll
        for (int r = 0; r < NRR; r++) {
            float d0 = r0 - mur[r];
            float d1 = r1 - mur[r];
            s_R2[v*NRR + r] = make_float2(ex2(d0*d0 * nisr[r]) * m0,
                                          ex2(d1*d1 * nisr[r]) * m1);
        }
    }
    // feat interleaved {b0,b1}
    for (int idx = tid; idx < VCS*2; idx += TPB) {
        int v = idx >> 1, h = idx & 1;
        float4 a = ((const float4*)(feat + (size_t)(b0*VV + cv0 + v)*FF))[h];
        float4 c = ((const float4*)(feat + (size_t)(b1*VV + cv0 + v)*FF))[h];
        float4* dst = (float4*)(s_F2 + v*FF + h*4);
        dst[0] = make_float4(a.x, c.x, a.y, c.y);
        dst[1] = make_float4(a.z, c.z, a.w, c.w);
    }
    __syncthreads();

    // phase 2: theta gaussians for both batches (t fixed per thread)
    for (int i = tid; i < VCS*NTT; i += TPB) {
        int v = i >> 4;
        float2 th = s_th[v];
        float d0 = th.x - mut0;
        float d1 = th.y - mut0;
        s_T2[i] = make_float2(ex2(d0*d0 * nist0), ex2(d1*d1 * nist0));
    }
    __syncthreads();

    const int g     = tid % GG;
    const int slice = tid / GG;
    const int r     = g >> 4;
    const int t     = g & 15;

    unsigned long long sum2 = 0ull;
    unsigned long long acc[FF];
    #pragma unroll
    for (int f = 0; f < FF; f++) acc[f] = 0ull;

    #pragma unroll 2
    for (int v = slice; v < VCS; v += NSLICE) {
        unsigned long long tv = *(const unsigned long long*)(s_T2 + v*NTT + t);
        unsigned long long rv = *(const unsigned long long*)(s_R2 + v*NRR + r);
        unsigned long long w2 = mul2(tv, rv);          // {w_b0, w_b1}
        add2(sum2, w2);
        const ulonglong2* fp = (const ulonglong2*)(s_F2 + v*FF);
        ulonglong2 p0 = fp[0];
        ulonglong2 p1 = fp[1];
        ulonglong2 p2 = fp[2];
        ulonglong2 p3 = fp[3];
        fma2(acc[0], w2, p0.x); fma2(acc[1], w2, p0.y);
        fma2(acc[2], w2, p1.x); fma2(acc[3], w2, p1.y);
        fma2(acc[4], w2, p2.x); fma2(acc[5], w2, p2.y);
        fma2(acc[6], w2, p3.x); fma2(acc[7], w2, p3.y);
    }
    __syncthreads();                    // vertex data dead; overlay reduction

    // packed reduction buffer: [320][9] ullong = 23040 B (overlays staging)
    unsigned long long* redU = (unsigned long long*)sm;
    {
        unsigned long long* dst = redU + tid*9;
        #pragma unroll
        for (int f = 0; f < FF; f++) dst[f] = acc[f];
        dst[8] = sum2;
    }
    __syncthreads();

    // combine 4 slices; 9 items x 80 g; split pair into the two batches
    const int bk0 = b0*NROT + k;
    const int bk1 = b1*NROT + k;
    for (int e = tid; e < 9*GG; e += TPB) {
        int item = e / GG;
        int gg   = e - item*GG;
        unsigned long long s = 0ull;
        #pragma unroll
        for (int sl = 0; sl < NSLICE; sl++)
            add2(s, redU[(sl*GG + gg)*9 + item]);
        float2 u = unpack2(s);
        int row = (item == 8) ? 0 : (1 + item);
        g_part[bk0][blockIdx.y][row][gg] = u.x;
        g_part[bk1][blockIdx.y][row][gg] = u.y;
    }
}

// ---------------------------------------------------------------------------
// Kernel A2: reduce chunks + normalize ONCE: g_part -> g_desc[bk][f*G+g].
// ---------------------------------------------------------------------------
__global__ void __launch_bounds__(GG)
normalize_kernel()
{
    const int bk = blockIdx.x;
    const int g  = threadIdx.x;
    float S[9];
    #pragma unroll
    for (int j = 0; j < 9; j++) S[j] = 0.0f;
    #pragma unroll
    for (int c = 0; c < VCH; c++)
        #pragma unroll
        for (int j = 0; j < 9; j++) S[j] += g_part[bk][c][j][g];
    float inv = 1.0f / (S[0] + EPSF);
    #pragma unroll
    for (int f = 0; f < FF; f++)
        g_desc[bk][f*GG + g] = S[1 + f] * inv;
}

// ---------------------------------------------------------------------------
// Kernel B: out[b,j] = relu(max_k desc_k@W[:,j] + bias[j]).
// 320 blocks (10 j-tiles x 32 b-pairs) x 256 threads (64 j x 4 i-segments).
// Contiguous desc prologue; 10 packed accs; packed segment combine.
// ---------------------------------------------------------------------------
__global__ void __launch_bounds__(TPBB)
gemm_max_relu_kernel(const float* __restrict__ Wm,
                     const float* __restrict__ bias,
                     float* __restrict__ out)
{
    __shared__ __align__(16) char smB[2*NROT*DD*4];    // 25600 B (union)
    float* s_desc = (float*)smB;                        // [10][640]
    unsigned long long* red = (unsigned long long*)smB; // [256][10] = 20480 B

    const int tid = threadIdx.x;
    const int b0  = blockIdx.y * 2;

    // rows bk = b0*5 .. b0*5+9 are contiguous in g_desc
    {
        const float4* src = (const float4*)g_desc[b0*NROT];
        float4* dst = (float4*)s_desc;
        for (int e = tid; e < 2*NROT*DD/4; e += TPBB)
            dst[e] = src[e];
    }
    __syncthreads();

    const int tx  = tid & 63;
    const int seg = tid >> 6;
    const int j   = blockIdx.x * 64 + tx;
    const int i0  = seg * (DD/4);                 // 160-row segment

    unsigned long long acc[10];
    #pragma unroll
    for (int a = 0; a < 10; a++) acc[a] = 0ull;

    #pragma unroll 8
    for (int i = i0; i < i0 + DD/4; i += 4) {
        float w0 = Wm[(i+0)*DD + j];
        float w1 = Wm[(i+1)*DD + j];
        float w2 = Wm[(i+2)*DD + j];
        float w3 = Wm[(i+3)*DD + j];
        unsigned long long wp0 = pack2(w0, w1);
        unsigned long long wp1 = pack2(w2, w3);
        #pragma unroll
        for (int a = 0; a < 10; a++) {
            ulonglong2 d = *(const ulonglong2*)&s_desc[a*DD + i];
            fma2(acc[a], d.x, wp0);
            fma2(acc[a], d.y, wp1);
        }
    }
    __syncthreads();                               // everyone done reading desc

    #pragma unroll
    for (int a = 0; a < 10; a++) red[tid*10 + a] = acc[a];
    __syncthreads();

    if (tid < 64) {
        const float bj = bias[j];
        #pragma unroll
        for (int bb = 0; bb < 2; bb++) {
            float m = -3.4e38f;
            #pragma unroll
            for (int kk = 0; kk < NROT; kk++) {
                int a = bb*NROT + kk;
                unsigned long long s = red[tid*10 + a];
                add2(s, red[(64  + tid)*10 + a]);
                add2(s, red[(128 + tid)*10 + a]);
                add2(s, red[(192 + tid)*10 + a]);
                float2 u = unpack2(s);
                m = fmaxf(m, u.x + u.y);
            }
            out[(b0 + bb)*DD + j] = fmaxf(m + bj, 0.0f);
        }
    }
}

// ---------------------------------------------------------------------------

extern "C" void kernel_launch(void* const* d_in, const int* in_sizes, int n_in,
                              void* d_out, int out_size) {
    const float* feat        = (const float*)d_in[0];
    const float* rho         = (const float*)d_in[1];
    const float* theta       = (const float*)d_in[2];
    const float* mask        = (const float*)d_in[3];
    const float* mu_rho      = (const float*)d_in[4];
    const float* sigma_rho   = (const float*)d_in[5];
    const float* mu_theta    = (const float*)d_in[6];
    const float* sigma_theta = (const float*)d_in[7];
    const float* Wm          = (const float*)d_in[8];
    const float* bias        = (const float*)d_in[9];
    float* out = (float*)d_out;

    const int smemA = 48000;
    cudaFuncSetAttribute(gauss_desc_kernel,
                         cudaFuncAttributeMaxDynamicSharedMemorySize, smemA);

    gauss_desc_kernel<<<dim3((BB/2)*NROT, VCH), TPB, smemA>>>(
        feat, rho, theta, mask, mu_rho, sigma_rho, mu_theta, sigma_theta);

    normalize_kernel<<<BB*NROT, GG>>>();

    gemm_max_relu_kernel<<<dim3(JT, BG), TPBB>>>(Wm, bias, out);
}